// round 17
// baseline (speedup 1.0000x reference)
#include <cuda_runtime.h>
#include <cstdint>

// B=8, N=2048, F=D=128
//   H = A_hat@X ; O = H@W^T + b ; out = relu(LN(O)*gamma+beta)
// Re-associated:  Y = X@W^T (tiny) ;  O = A_hat@Y  ->  fused LN+ReLU epilogue.
//
// R16 = R15 ring/pipeline with 8 warps per CTA (256 thr, warp grid 2m x 4n,
// warp tile 32x32). Grid stays 256 CTAs; warps/SMSP 1.73 -> 3.46 to fill
// the ~500 cyc/chunk bubbles identified at 2-warp residency.

#define BATCH 8
#define NN    2048
#define FF    128
#define ROWS  64
#define CK    32
#define NCH   64
#define PADA  36             // stage pitch (36 % 32 == 4 -> LDSM conflict-free)
#define PADW  132            // y_kernel tile pitch

#define ST_Y_OFF  9216       // A part 64*36*4
#define STAGE_B   27648      // + Y part 128*36*4 = 18432
#define SM_MBAR   110592     // full[4] @ +0, empty[4] @ +32
#define SM_PAR    110656     // bias|gamma|beta 3*512
#define SM_RED    112192     // 64 rows x 4 wn x {s1,s2} = 2048
#define SM_TOTAL  114240     // x2 CTAs = 228480 <= 233472

#define SM_Y_TOTAL 101376    // y_kernel: W 128*132*4 + X 64*132*4

__device__ __align__(16) float g_Yt[BATCH * FF * NN];   // 8 MB scratch

__device__ __forceinline__ uint32_t smem_u32(const void* p) {
    uint32_t a;
    asm("{ .reg .u64 t; cvta.to.shared.u64 t, %1; cvt.u32.u64 %0, t; }" : "=r"(a) : "l"(p));
    return a;
}
__device__ __forceinline__ void cp16(uint32_t dst, const void* src) {
    asm volatile("cp.async.cg.shared.global [%0], [%1], 16;" :: "r"(dst), "l"(src) : "memory");
}

#define MBAR_INIT(mb, c)  asm volatile("mbarrier.init.shared.b64 [%0], %1;" :: "r"(mb), "r"(c) : "memory")
#define MBAR_ARRIVE(mb)   asm volatile("mbarrier.arrive.shared.b64 _, [%0];" :: "r"(mb) : "memory")
#define CP_ARRIVE(mb)     asm volatile("cp.async.mbarrier.arrive.noinc.shared::cta.b64 [%0];" :: "r"(mb) : "memory")

#define MBAR_WAIT(mb, ph) do {                                                     \
    uint32_t _m = (mb); uint32_t _p = (ph); uint32_t _d;                           \
    asm volatile("{\n\t.reg .pred p;\n\t"                                          \
        "mbarrier.try_wait.parity.acquire.cta.shared::cta.b64 p, [%1], %2;\n\t"    \
        "selp.b32 %0, 1, 0, p;\n\t}" : "=r"(_d) : "r"(_m), "r"(_p) : "memory");    \
    if (!_d) {                                                                     \
        asm volatile("{\n\t.reg .pred P1;\n\t"                                     \
        "W_%=:\n\t"                                                                \
        "mbarrier.try_wait.parity.acquire.cta.shared::cta.b64 P1, [%0], %1, 0x989680;\n\t" \
        "@P1 bra.uni D_%=;\n\tbra.uni W_%=;\n\tD_%=:\n\t}"                         \
        :: "r"(_m), "r"(_p) : "memory");                                           \
    }                                                                              \
} while (0)

#define LDSM_X4(r0, r1, r2, r3, addr)                                           \
    asm volatile("ldmatrix.sync.aligned.m8n8.x4.shared.b16 {%0,%1,%2,%3}, [%4];"\
        : "=r"(r0), "=r"(r1), "=r"(r2), "=r"(r3) : "r"(addr))

#define MMA_TF32(d, av, bv)                                                     \
    asm volatile("mma.sync.aligned.m16n8k8.row.col.f32.tf32.tf32.f32 "          \
        "{%0,%1,%2,%3}, {%4,%5,%6,%7}, {%8,%9}, {%0,%1,%2,%3};"                 \
        : "+f"((d)[0]), "+f"((d)[1]), "+f"((d)[2]), "+f"((d)[3])                \
        : "r"((av)[0]), "r"((av)[1]), "r"((av)[2]), "r"((av)[3]),               \
          "r"((bv)[0]), "r"((bv)[1]))

// ---------------- k0: Yt[b][d][n] = sum_f X[b][n][f] * W[d][f] ----------------
// grid (32 n-tiles of 64, 8 batches), 256 thr; warp tile 32(d) x 32(n)
__global__ __launch_bounds__(256, 1)
void y_kernel(const float* __restrict__ X, const float* __restrict__ W) {
    extern __shared__ char ysm[];
    float* sW = (float*)ysm;                         // [128][132]
    float* sX = (float*)(ysm + 67584);               // [64][132]
    const uint32_t wU = smem_u32(sW);
    const uint32_t xU = smem_u32(sX);

    const int tid = threadIdx.x;
    const int lid = tid & 31;
    const int wid = tid >> 5;
    const int wm  = wid >> 1, wn = wid & 1;
    const int gp  = lid >> 2, tg = lid & 3;
    const int s   = lid >> 3, rr = lid & 7;
    const int aR = (s & 1) * 8 + rr, aC = (s >> 1) * 4;
    const int bR = (s >> 1) * 8 + rr, bC = (s & 1) * 4;

    const int n0 = blockIdx.x * 64;
    const int bt = blockIdx.y;
    const float* Xb = X + (size_t)bt * NN * FF + (size_t)n0 * FF;

#pragma unroll
    for (int i = 0; i < 16; i++) {
        int id = tid + i * 256;
        int r = id >> 5, q = id & 31;
        *(float4*)(sW + r * PADW + q * 4) = *(const float4*)(W + (size_t)r * FF + q * 4);
    }
#pragma unroll
    for (int i = 0; i < 8; i++) {
        int id = tid + i * 256;
        int r = id >> 5, q = id & 31;
        *(float4*)(sX + r * PADW + q * 4) = *(const float4*)(Xb + (size_t)r * FF + q * 4);
    }
    __syncthreads();

    float acc[2][4][4];
#pragma unroll
    for (int i = 0; i < 2; i++)
#pragma unroll
        for (int j = 0; j < 4; j++)
#pragma unroll
            for (int k = 0; k < 4; k++) acc[i][j][k] = 0.f;

#pragma unroll
    for (int k8 = 0; k8 < 16; k8++) {
        const int kb = k8 * 8;
        uint32_t af[2][4], bf[4][2];
#pragma unroll
        for (int mt = 0; mt < 2; mt++) {
            uint32_t ad = wU + (uint32_t)((wm * 32 + mt * 16 + aR) * PADW + kb + aC) * 4u;
            LDSM_X4(af[mt][0], af[mt][1], af[mt][2], af[mt][3], ad);
        }
#pragma unroll
        for (int p = 0; p < 2; p++) {
            uint32_t bd = xU + (uint32_t)((wn * 32 + p * 16 + bR) * PADW + kb + bC) * 4u;
            LDSM_X4(bf[p * 2][0], bf[p * 2][1], bf[p * 2 + 1][0], bf[p * 2 + 1][1], bd);
        }
#pragma unroll
        for (int mt = 0; mt < 2; mt++)
#pragma unroll
            for (int nt = 0; nt < 4; nt++)
                MMA_TF32(acc[mt][nt], af[mt], bf[nt]);
    }

    float* Yb = g_Yt + (size_t)bt * FF * NN;
#pragma unroll
    for (int mt = 0; mt < 2; mt++)
#pragma unroll
        for (int h = 0; h < 2; h++) {
            int d = wm * 32 + mt * 16 + h * 8 + gp;
#pragma unroll
            for (int nt = 0; nt < 4; nt++) {
                int n = n0 + wn * 32 + nt * 8 + 2 * tg;
                *(float2*)(Yb + (size_t)d * NN + n) =
                    make_float2(acc[mt][nt][h * 2 + 0], acc[mt][nt][h * 2 + 1]);
            }
        }
}

// ---------------- k1: fused O = A@Yt -> bias+LN+ReLU (8 warps) ----------------
__global__ __launch_bounds__(256, 2)
void fused_kernel(const float* __restrict__ A,
                  const float* __restrict__ bias, const float* __restrict__ gamma,
                  const float* __restrict__ beta, float* __restrict__ out) {
    extern __shared__ char smem[];
    float* sf = (float*)smem;
    const uint32_t sbu = smem_u32(smem);

    const int tid = threadIdx.x;
    const int lid = tid & 31;
    const int wid = tid >> 5;           // 0..7
    const int wm  = wid >> 2;           // 0..1: 32-row half
    const int wn  = wid & 3;            // 0..3: 32-col quarter
    const int gp  = lid >> 2, tg = lid & 3;
    const int s   = lid >> 3, rr = lid & 7;
    const int aR = (s & 1) * 8 + rr, aC = (s >> 1) * 4;
    const int bR = (s >> 1) * 8 + rr, bC = (s & 1) * 4;

    const int bt      = blockIdx.x >> 5;
    const int rowTile = blockIdx.x & 31;
    const float* Ab = A    + (size_t)bt * NN * NN + (size_t)rowTile * ROWS * NN;
    const float* Yb = g_Yt + (size_t)bt * FF * NN;

    if (tid == 0) {
#pragma unroll
        for (int st = 0; st < 4; st++) {
            MBAR_INIT(sbu + SM_MBAR + st * 8, 256);     // full: cp.async arrivals (256 thr)
            MBAR_INIT(sbu + SM_MBAR + 32 + st * 8, 8);  // empty: 8 warp arrivals
        }
    }
    if (tid < 128) {
        sf[SM_PAR / 4 + tid]       = bias[tid];
        sf[SM_PAR / 4 + 128 + tid] = gamma[tid];
        sf[SM_PAR / 4 + 256 + tid] = beta[tid];
    }
    __syncthreads();

    float acc[2][4][4];                 // 32x32 warp tile
#pragma unroll
    for (int i = 0; i < 2; i++)
#pragma unroll
        for (int j = 0; j < 4; j++)
#pragma unroll
            for (int k = 0; k < 4; k++) acc[i][j][k] = 0.f;

    // 256 threads: A 512 float4 (2/thread), Y 1024 float4 (4/thread)
    auto load_chunk = [&](int c) {
        const int st = c & 3;
        const uint32_t ab = sbu + (uint32_t)st * STAGE_B;
        const uint32_t yb = ab + ST_Y_OFF;
        const float* ga = Ab + c * CK;
        const float* gy = Yb + c * CK;
#pragma unroll
        for (int i = 0; i < 2; i++) {
            int ia = tid + i * 256;
            int ra = ia >> 3, qa = ia & 7;
            cp16(ab + (uint32_t)(ra * PADA + qa * 4) * 4u, ga + (size_t)ra * NN + qa * 4);
        }
#pragma unroll
        for (int i = 0; i < 4; i++) {
            int iy = tid + i * 256;
            int ry = iy >> 3, qy = iy & 7;
            cp16(yb + (uint32_t)(ry * PADA + qy * 4) * 4u, gy + (size_t)ry * NN + qy * 4);
        }
        CP_ARRIVE(sbu + SM_MBAR + st * 8);
    };

    load_chunk(0); load_chunk(1); load_chunk(2);

    uint32_t af[2][2][4], bf[2][4][2];  // double-buffered fragments

    auto ldA = [&](uint32_t base, int kb, int buf) {
#pragma unroll
        for (int mt = 0; mt < 2; mt++) {
            uint32_t ad = base + (uint32_t)((wm * 32 + mt * 16 + aR) * PADA + kb + aC) * 4u;
            LDSM_X4(af[buf][mt][0], af[buf][mt][1], af[buf][mt][2], af[buf][mt][3], ad);
        }
    };
    auto ldB = [&](uint32_t base, int kb, int buf) {
#pragma unroll
        for (int p = 0; p < 2; p++) {
            uint32_t bd = base + (uint32_t)((wn * 32 + p * 16 + bR) * PADA + kb + bC) * 4u;
            LDSM_X4(bf[buf][p * 2][0], bf[buf][p * 2][1],
                    bf[buf][p * 2 + 1][0], bf[buf][p * 2 + 1][1], bd);
        }
    };

#define MMA_BLOCK(buf)                                                          \
    _Pragma("unroll")                                                           \
    for (int mt = 0; mt < 2; mt++)                                              \
        _Pragma("unroll")                                                       \
        for (int nt = 0; nt < 4; nt++)                                          \
            MMA_TF32(acc[mt][nt], af[buf][mt], bf[buf][nt]);

    // ---- prologue: wait chunk 0, load its k8=0 fragments into buf0 ----
    MBAR_WAIT(sbu + SM_MBAR + 0, 0);
    ldA(sbu, 0, 0); ldB(sbu + ST_Y_OFF, 0, 0);

    for (int c = 0; c < NCH; c++) {
        const int st = c & 3;
        const uint32_t aBase = sbu + (uint32_t)st * STAGE_B;
        const uint32_t yBase = aBase + ST_Y_OFF;
        // k8=0: load k8=1 frags -> buf1; MMA buf0
        ldA(aBase, 8, 1);  ldB(yBase, 8, 1);
        MMA_BLOCK(0)
        // k8=1: load k8=2 frags -> buf0; MMA buf1; then prefetch chunk c+3
        ldA(aBase, 16, 0); ldB(yBase, 16, 0);
        MMA_BLOCK(1)
        if (c + 3 < NCH) {
            const int cc = c + 3, st3 = cc & 3;
            if (cc >= 4) MBAR_WAIT(sbu + SM_MBAR + 32 + st3 * 8, ((cc >> 2) - 1) & 1);
            load_chunk(cc);
        }
        // k8=2: load k8=3 frags -> buf1 (last read of stage st) -> arrive empty; MMA buf0
        ldA(aBase, 24, 1); ldB(yBase, 24, 1);
        if (lid == 0) MBAR_ARRIVE(sbu + SM_MBAR + 32 + st * 8);
        MMA_BLOCK(0)
        // k8=3: wait full[c+1] (fast-path), load (c+1, k8=0) -> buf0; MMA buf1
        if (c + 1 < NCH) {
            const int cn = c + 1, stn = cn & 3;
            MBAR_WAIT(sbu + SM_MBAR + stn * 8, (cn >> 2) & 1);
            const uint32_t aN = sbu + (uint32_t)stn * STAGE_B;
            ldA(aN, 0, 0); ldB(aN + ST_Y_OFF, 0, 0);
        }
        MMA_BLOCK(1)
    }

    // ---- epilogue: bias + LayerNorm + ReLU ----
    const float* sbias = sf + SM_PAR / 4;
    const float* sgam  = sbias + 128;
    const float* sbet  = sbias + 256;
    float* sred = sf + SM_RED / 4;

    float s1[2][2], s2[2][2];
#pragma unroll
    for (int mt = 0; mt < 2; mt++) { s1[mt][0] = s1[mt][1] = s2[mt][0] = s2[mt][1] = 0.f; }
#pragma unroll
    for (int mt = 0; mt < 2; mt++)
#pragma unroll
        for (int nt = 0; nt < 4; nt++) {
            int cc = wn * 32 + nt * 8 + 2 * tg;
            float b0 = sbias[cc], b1 = sbias[cc + 1];
            float v0 = acc[mt][nt][0] + b0, v1 = acc[mt][nt][1] + b1;
            float v2 = acc[mt][nt][2] + b0, v3 = acc[mt][nt][3] + b1;
            acc[mt][nt][0] = v0; acc[mt][nt][1] = v1;
            acc[mt][nt][2] = v2; acc[mt][nt][3] = v3;
            s1[mt][0] += v0 + v1;           s2[mt][0] += v0 * v0 + v1 * v1;
            s1[mt][1] += v2 + v3;           s2[mt][1] += v2 * v2 + v3 * v3;
        }
#pragma unroll
    for (int mt = 0; mt < 2; mt++)
#pragma unroll
        for (int h = 0; h < 2; h++) {
            s1[mt][h] += __shfl_xor_sync(0xffffffffu, s1[mt][h], 1);
            s1[mt][h] += __shfl_xor_sync(0xffffffffu, s1[mt][h], 2);
            s2[mt][h] += __shfl_xor_sync(0xffffffffu, s2[mt][h], 1);
            s2[mt][h] += __shfl_xor_sync(0xffffffffu, s2[mt][h], 2);
        }
    if (tg == 0) {
#pragma unroll
        for (int mt = 0; mt < 2; mt++)
#pragma unroll
            for (int h = 0; h < 2; h++) {
                int r = wm * 32 + mt * 16 + h * 8 + gp;
                sred[r * 8 + wn * 2 + 0] = s1[mt][h];
                sred[r * 8 + wn * 2 + 1] = s2[mt][h];
            }
    }
    __syncthreads();

    float* outBase = out + ((size_t)bt * NN + (size_t)rowTile * ROWS) * FF;
#pragma unroll
    for (int mt = 0; mt < 2; mt++)
#pragma unroll
        for (int h = 0; h < 2; h++) {
            int r = wm * 32 + mt * 16 + h * 8 + gp;
            float S1 = sred[r * 8 + 0] + sred[r * 8 + 2] + sred[r * 8 + 4] + sred[r * 8 + 6];
            float S2 = sred[r * 8 + 1] + sred[r * 8 + 3] + sred[r * 8 + 5] + sred[r * 8 + 7];
            float mean = S1 * (1.0f / 128.0f);
            float var  = S2 * (1.0f / 128.0f) - mean * mean;
            float inv  = rsqrtf(var + 1e-5f);
            float* orow = outBase + (size_t)r * FF;
#pragma unroll
            for (int nt = 0; nt < 4; nt++) {
                int cc = wn * 32 + nt * 8 + 2 * tg;
                float v0 = acc[mt][nt][h * 2 + 0];
                float v1 = acc[mt][nt][h * 2 + 1];
                float o0 = fmaxf((v0 - mean) * inv * sgam[cc]     + sbet[cc],     0.f);
                float o1 = fmaxf((v1 - mean) * inv * sgam[cc + 1] + sbet[cc + 1], 0.f);
                *(float2*)(orow + cc) = make_float2(o0, o1);
            }
        }
}

// ---------------- launch ----------------
extern "C" void kernel_launch(void* const* d_in, const int* in_sizes, int n_in,
                              void* d_out, int out_size) {
    const float* A     = (const float*)d_in[0];   // [8,2048,2048]
    const float* X     = (const float*)d_in[1];   // [8,2048,128]
    const float* W     = (const float*)d_in[2];   // [128,128]
    const float* bias  = (const float*)d_in[3];
    const float* gamma = (const float*)d_in[4];
    const float* beta  = (const float*)d_in[5];
    float* out = (float*)d_out;

    cudaFuncSetAttribute(y_kernel, cudaFuncAttributeMaxDynamicSharedMemorySize, SM_Y_TOTAL);
    cudaFuncSetAttribute(fused_kernel, cudaFuncAttributeMaxDynamicSharedMemorySize, SM_TOTAL);

    y_kernel<<<dim3(NN / 64, BATCH), 256, SM_Y_TOTAL>>>(X, W);
    fused_kernel<<<BATCH * (NN / ROWS), 256, SM_TOTAL>>>(A, bias, gamma, beta, out);
}